// round 5
// baseline (speedup 1.0000x reference)
#include <cuda_runtime.h>

#define NBLK 128
#define NTHR 256
#define LDS_ 132   // padded smem row stride (floats): 528B, 16B-aligned, conflict-free float4
typedef unsigned long long u64;

// Scratch (allocation-free rule: __device__ globals)
__device__ float g_h0[512 * 128];    // x @ fp_W + fp_b
__device__ float g_r[512 * 512];     // relu(h0 @ gat_W^T)
__device__ float g_opWt[128 * 512];  // op_W transposed: [n][k]
__device__ unsigned g_cnt = 0;       // barrier arrivals (returns to 0 every launch)
__device__ unsigned g_gen = 0;       // barrier generation (monotonic across launches — fine)

__device__ __forceinline__ void grid_barrier()
{
    __threadfence();
    __syncthreads();
    if (threadIdx.x == 0) {
        unsigned gen = *(volatile unsigned*)&g_gen;   // read BEFORE arriving
        unsigned t = atomicAdd(&g_cnt, 1u);
        if (t == NBLK - 1) {
            g_cnt = 0;
            __threadfence();
            atomicAdd(&g_gen, 1u);                    // release
        } else {
            while (*(volatile unsigned*)&g_gen == gen) { }
        }
    }
    __syncthreads();
}

__device__ __forceinline__ u64 ffma2(u64 a, u64 b, u64 c) {
    u64 d;
    asm("fma.rn.f32x2 %0, %1, %2, %3;" : "=l"(d) : "l"(a), "l"(b), "l"(c));
    return d;
}
__device__ __forceinline__ float f2lo(u64 v) { return __uint_as_float((unsigned)v); }
__device__ __forceinline__ float f2hi(u64 v) { return __uint_as_float((unsigned)(v >> 32)); }

// Warp tile: 4 m-rows (As, broadcast reads) x 64 n-cols (lane + 32j, strided
// conflict-free) over one K=128 chunk. acc packs (even k, odd k) in f32x2.
__device__ __forceinline__ void wtile4(const float* __restrict__ As,
                                       const float* __restrict__ Bs,
                                       int lane, u64 acc[4][2])
{
    #pragma unroll 4
    for (int k4 = 0; k4 < 32; k4++) {
        ulonglong2 b0 = *(const ulonglong2*)(Bs + (size_t)lane        * LDS_ + k4 * 4);
        ulonglong2 b1 = *(const ulonglong2*)(Bs + (size_t)(lane + 32) * LDS_ + k4 * 4);
        #pragma unroll
        for (int i = 0; i < 4; i++) {
            ulonglong2 a = *(const ulonglong2*)(As + (size_t)i * LDS_ + k4 * 4);
            acc[i][0] = ffma2(a.x, b0.x, acc[i][0]);
            acc[i][0] = ffma2(a.y, b0.y, acc[i][0]);
            acc[i][1] = ffma2(a.x, b1.x, acc[i][1]);
            acc[i][1] = ffma2(a.y, b1.y, acc[i][1]);
        }
    }
}

__global__ void __launch_bounds__(NTHR, 1)
fused_kernel(const float* __restrict__ x,   const float* __restrict__ mask,
             const float* __restrict__ emb, const float* __restrict__ gatW,
             const float* __restrict__ fpW, const float* __restrict__ fpb,
             const float* __restrict__ opW, const float* __restrict__ opb,
             const int*   __restrict__ kp,  float* __restrict__ out)
{
    extern __shared__ float sm[];
    const int blk = blockIdx.x, t = threadIdx.x, lane = t & 31, w = t >> 5;

    // ═ Phase 0: adj (0..63) ∥ h0 GEMM (64..95) ∥ opW transpose (96..127) ═══
    if (blk < 64) {
        // cosine-sim top-k adjacency rows 2blk, 2blk+1 (lower index wins ties)
        float* es    = sm;                 // 128 x LDS_
        float* s_n2  = sm + 128 * LDS_;    // 128
        float* s_sim = s_n2 + 128;         // 2 x 128 (16B aligned)
        #pragma unroll
        for (int i = 0; i < 16; i++) {
            int idx = t + i * 256; int r = idx >> 5, c4 = idx & 31;
            *(float4*)(es + r * LDS_ + c4 * 4) =
                *(const float4*)(emb + (size_t)r * 128 + c4 * 4);
        }
        __syncthreads();
        const int rr = t >> 7, j = t & 127;
        const int irow = blk * 2 + rr;
        const float* ei = es + irow * LDS_;
        const float* ej = es + j * LDS_;
        float dij = 0.f, nj = 0.f;
        #pragma unroll 8
        for (int f4 = 0; f4 < 32; f4++) {
            float4 b = *(const float4*)(ej + f4 * 4);
            float4 a = *(const float4*)(ei + f4 * 4);
            dij += a.x * b.x + a.y * b.y + a.z * b.z + a.w * b.w;
            nj  += b.x * b.x + b.y * b.y + b.z * b.z + b.w * b.w;
        }
        if (rr == 0) s_n2[j] = nj;
        __syncthreads();
        float sim = dij / (sqrtf(s_n2[irow]) * sqrtf(nj));
        s_sim[rr * 128 + j] = sim;
        __syncthreads();
        const float4* S = (const float4*)(s_sim + rr * 128);
        int cnt = 0;
        #pragma unroll 8
        for (int q = 0; q < 32; q++) {
            float4 a = S[q];
            int base = q * 4;
            cnt += (a.x > sim) || (a.x == sim && base + 0 < j);
            cnt += (a.y > sim) || (a.y == sim && base + 1 < j);
            cnt += (a.z > sim) || (a.z == sim && base + 2 < j);
            cnt += (a.w > sim) || (a.w == sim && base + 3 < j);
        }
        out[65536 + irow * 128 + j] = (cnt < kp[0]) ? 1.0f : 0.0f;
    } else if (blk < 96) {
        // h0 tile [32 x 64]: h0 = x @ fp_W + fp_b, K=128
        int tt = blk - 64;
        int m0 = (tt >> 1) * 32, n0 = (tt & 1) * 64;
        float* As = sm;               // 32 x LDS_
        float* Bs = sm + 32 * LDS_;   // 64 x LDS_  (row = n_local, col = k)
        #pragma unroll
        for (int i = 0; i < 4; i++) {
            int idx = t + i * 256; int r = idx >> 5, c4 = idx & 31;
            *(float4*)(As + r * LDS_ + c4 * 4) =
                *(const float4*)(x + (size_t)(m0 + r) * 128 + c4 * 4);
        }
        // transpose fp_W cols [n0, n0+64): thread (kk, half) owns k-row kk, 4 n's
        {
            int kk = t & 127, half = t >> 7;
            #pragma unroll
            for (int p4 = 0; p4 < 8; p4++) {
                float4 v = *(const float4*)(fpW + (size_t)kk * 128 + n0 + (half * 8 + p4) * 4);
                Bs[((half * 8 + p4) * 4 + 0) * LDS_ + kk] = v.x;
                Bs[((half * 8 + p4) * 4 + 1) * LDS_ + kk] = v.y;
                Bs[((half * 8 + p4) * 4 + 2) * LDS_ + kk] = v.z;
                Bs[((half * 8 + p4) * 4 + 3) * LDS_ + kk] = v.w;
            }
        }
        __syncthreads();
        u64 acc[4][2];
        #pragma unroll
        for (int i = 0; i < 4; i++) { acc[i][0] = 0ull; acc[i][1] = 0ull; }
        wtile4(As + (size_t)(w * 4) * LDS_, Bs, lane, acc);
        #pragma unroll
        for (int i = 0; i < 4; i++) {
            int m = m0 + w * 4 + i;
            #pragma unroll
            for (int j = 0; j < 2; j++) {
                int n = n0 + lane + 32 * j;
                g_h0[(size_t)m * 128 + n] = f2lo(acc[i][j]) + f2hi(acc[i][j]) + fpb[n];
            }
        }
    } else {
        // opW transpose: block handles k-slice [(blk-96)*16, +16), thread = (n, half)
        int k0 = (blk - 96) * 16;
        int n = t & 127, half = t >> 7;
        float v[8];
        #pragma unroll
        for (int kk = 0; kk < 8; kk++)
            v[kk] = opW[(size_t)(k0 + half * 8 + kk) * 128 + n];
        #pragma unroll
        for (int q = 0; q < 2; q++)
            *(float4*)(g_opWt + (size_t)n * 512 + k0 + half * 8 + q * 4) =
                make_float4(v[q * 4], v[q * 4 + 1], v[q * 4 + 2], v[q * 4 + 3]);
    }
    grid_barrier();

    // ═ Phase 1: r = relu(h0 @ gat_W^T), 512x512 — 128 tiles of [32 x 64] ════
    {
        float* As = sm;               // 32 x LDS_
        float* Bs = sm + 32 * LDS_;   // 64 x LDS_
        const int m0 = (blk >> 3) * 32, c0 = (blk & 7) * 64;
        #pragma unroll
        for (int i = 0; i < 4; i++) {
            int idx = t + i * 256; int r = idx >> 5, c4 = idx & 31;
            *(float4*)(As + r * LDS_ + c4 * 4) =
                *(const float4*)(g_h0 + (size_t)(m0 + r) * 128 + c4 * 4);
        }
        #pragma unroll
        for (int i = 0; i < 8; i++) {
            int idx = t + i * 256; int r = idx >> 5, c4 = idx & 31;
            *(float4*)(Bs + r * LDS_ + c4 * 4) =
                *(const float4*)(gatW + (size_t)(c0 + r) * 128 + c4 * 4);
        }
        __syncthreads();
        u64 acc[4][2];
        #pragma unroll
        for (int i = 0; i < 4; i++) { acc[i][0] = 0ull; acc[i][1] = 0ull; }
        wtile4(As + (size_t)(w * 4) * LDS_, Bs, lane, acc);
        #pragma unroll
        for (int i = 0; i < 4; i++) {
            int m = m0 + w * 4 + i;
            #pragma unroll
            for (int j = 0; j < 2; j++) {
                int c = c0 + lane + 32 * j;
                g_r[(size_t)m * 512 + c] = fmaxf(f2lo(acc[i][j]) + f2hi(acc[i][j]), 0.0f);
            }
        }
    }
    grid_barrier();

    // ═ Phase 2: out = x(1-mask) + (r @ op_W + op_b)·mask — tiles [8m x 64n].
    //   4-way K-split across warp-PAIRS (group g = w>>1 owns K chunk g);
    //   within a pair, wg = w&1 takes 4 of the 8 m-rows. ═════════════════════
    {
        float* As = sm;               // [4 chunks][8 rows][LDS_]
        float* Bs = sm + 32 * LDS_;   // [4 groups][64 rows][LDS_]
        float* red = sm;              // reuse As region after sync: 4*512 floats
        const int m0 = (blk >> 1) * 8, n0 = (blk & 1) * 64;
        const int g = w >> 1, wg = w & 1;

        #pragma unroll
        for (int i = 0; i < 4; i++) {
            int idx = t + i * 256;          // over (m 0..7) x (kq 0..127 float4)
            int m = idx >> 7, kq = idx & 127;
            int c = kq >> 5, kl = kq & 31;
            *(float4*)(As + (size_t)(c * 8 + m) * LDS_ + kl * 4) =
                *(const float4*)(g_r + (size_t)(m0 + m) * 512 + kq * 4);
        }
        {
            int tp = wg * 32 + lane;        // 0..63 within pair
            #pragma unroll
            for (int h = 0; h < 32; h++) {
                int idx = tp + h * 64;      // over (row 0..63) x (k4 0..31)
                int row = idx >> 5, k4 = idx & 31;
                *(float4*)(Bs + (size_t)(g * 64 + row) * LDS_ + k4 * 4) =
                    *(const float4*)(g_opWt + (size_t)(n0 + row) * 512 + g * 128 + k4 * 4);
            }
        }
        __syncthreads();
        u64 acc[4][2];
        #pragma unroll
        for (int i = 0; i < 4; i++) { acc[i][0] = 0ull; acc[i][1] = 0ull; }
        wtile4(As + (size_t)(g * 8 + wg * 4) * LDS_, Bs + (size_t)(g * 64) * LDS_, lane, acc);
        __syncthreads();
        #pragma unroll
        for (int i = 0; i < 4; i++)
            #pragma unroll
            for (int j = 0; j < 2; j++)
                red[g * 512 + (wg * 4 + i) * 64 + lane + 32 * j] =
                    f2lo(acc[i][j]) + f2hi(acc[i][j]);
        __syncthreads();
        #pragma unroll
        for (int q = 0; q < 2; q++) {
            int o = t + q * 256;            // 0..511
            int m = o >> 6, n = o & 63;
            float v = red[o] + red[512 + o] + red[1024 + o] + red[1536 + o] + opb[n0 + n];
            size_t gi = (size_t)(m0 + m) * 128 + n0 + n;
            float xv = x[gi], mv = mask[gi];
            out[gi] = xv * (1.0f - mv) + v * mv;
        }
    }
}

extern "C" void kernel_launch(void* const* d_in, const int* in_sizes, int n_in,
                              void* d_out, int out_size)
{
    const float* x    = (const float*)d_in[0];
    const float* mask = (const float*)d_in[1];
    const float* emb  = (const float*)d_in[2];
    const float* gatW = (const float*)d_in[3];
    // d_in[4] = gat_a: provably unused (softmax over constant logits -> adj/k; rows sum to 1)
    const float* fpW  = (const float*)d_in[5];
    const float* fpb  = (const float*)d_in[6];
    const float* opW  = (const float*)d_in[7];
    const float* opb  = (const float*)d_in[8];
    const int*   kp   = (const int*)d_in[9];
    float* out = (float*)d_out;

    // max over phases: phase2 = (32 + 256) * LDS_ floats = 152064 B
    const int SMEM = (32 + 256) * LDS_ * 4;
    cudaFuncSetAttribute(fused_kernel, cudaFuncAttributeMaxDynamicSharedMemorySize, SMEM);
    fused_kernel<<<NBLK, NTHR, SMEM>>>(x, mask, emb, gatW, fpW, fpb, opW, opb, kp, out);
}